// round 1
// baseline (speedup 1.0000x reference)
#include <cuda_runtime.h>
#include <math.h>

// ---------------------------------------------------------------------------
// NormLinearAttention  B=2 N=2048 D=1024 H=16 DH=64
// Right-form linear attention: out = q' @ (k'^T v)  (KV is [128,64] per head)
// Pipeline:
//   1. sgemm_nt : qkvu = x @ Wqkvu^T + b          [4096,4096]
//   2. kv_kernel: partial KV per (chunk,b,h)       (silu+lrpe on k fused)
//   3. kv_reduce: deterministic sum of 8 partials
//   4. qout_kernel: attn = q' @ KV                 (silu+lrpe on q fused)
//   5. ln_kernel : LayerNorm + *u
//   6. sgemm_nt : out = normed @ Wout^T + bout
// ---------------------------------------------------------------------------

#define Bb 2
#define Nn 2048
#define Dd 1024
#define Hh 16
#define DH 64
#define MROWS (Bb*Nn)        // 4096

// scratch (no dynamic allocation allowed)
__device__ float g_qkvu[(size_t)MROWS * 4 * Dd];     // 64 MB
__device__ float g_kvp[8 * 32 * 128 * 64];            // 8 MB partial KV
__device__ float g_kv[32 * 128 * 64];                 // 1 MB reduced KV
__device__ float g_attn[(size_t)MROWS * Dd];          // 16 MB
__device__ float g_norm[(size_t)MROWS * Dd];          // 16 MB

// ---------------------------------------------------------------------------
// C[m,n] = sum_k A[m,k] * B[n,k] + bias[n]   (both row-major, K contiguous)
// 128x128 tile, K-tile 8, 256 threads, 8x8 per thread.
// ---------------------------------------------------------------------------
__global__ __launch_bounds__(256, 2)
void sgemm_nt(const float* __restrict__ A, const float* __restrict__ B,
              const float* __restrict__ bias, float* __restrict__ C,
              int M, int N, int K)
{
    __shared__ float sA[8][128];
    __shared__ float sB[8][128];

    const int tid = threadIdx.x;
    const int bm = blockIdx.y * 128;
    const int bn = blockIdx.x * 128;
    const int lr = tid >> 1;            // 0..127 tile row for loads
    const int lk = (tid & 1) << 2;      // 0 or 4
    const int tx = tid & 15;
    const int ty = tid >> 4;

    const float* Ap = A + (size_t)(bm + lr) * K + lk;
    const float* Bp = B + (size_t)(bn + lr) * K + lk;

    float acc[8][8];
#pragma unroll
    for (int i = 0; i < 8; i++)
#pragma unroll
        for (int j = 0; j < 8; j++) acc[i][j] = 0.f;

    for (int k0 = 0; k0 < K; k0 += 8) {
        float4 a4 = *(const float4*)(Ap + k0);
        float4 b4 = *(const float4*)(Bp + k0);
        __syncthreads();
        sA[lk + 0][lr] = a4.x; sA[lk + 1][lr] = a4.y;
        sA[lk + 2][lr] = a4.z; sA[lk + 3][lr] = a4.w;
        sB[lk + 0][lr] = b4.x; sB[lk + 1][lr] = b4.y;
        sB[lk + 2][lr] = b4.z; sB[lk + 3][lr] = b4.w;
        __syncthreads();
#pragma unroll
        for (int kk = 0; kk < 8; kk++) {
            float a[8], b[8];
            *(float4*)&a[0] = *(const float4*)&sA[kk][ty * 8];
            *(float4*)&a[4] = *(const float4*)&sA[kk][ty * 8 + 4];
            *(float4*)&b[0] = *(const float4*)&sB[kk][tx * 8];
            *(float4*)&b[4] = *(const float4*)&sB[kk][tx * 8 + 4];
#pragma unroll
            for (int i = 0; i < 8; i++)
#pragma unroll
                for (int j = 0; j < 8; j++)
                    acc[i][j] = fmaf(a[i], b[j], acc[i][j]);
        }
    }

#pragma unroll
    for (int i = 0; i < 8; i++) {
        const int row = bm + ty * 8 + i;
        float* Crow = C + (size_t)row * N + bn + tx * 8;
#pragma unroll
        for (int j = 0; j < 8; j++)
            Crow[j] = acc[i][j] + bias[bn + tx * 8 + j];
    }
}

__device__ __forceinline__ float silu_f(float x) {
    return x / (1.f + expf(-x));
}

// ---------------------------------------------------------------------------
// Partial KV: for (b,h), chunk of 256 tokens -> KV_part[128][64]
// k'[n,d]     = silu(k[n,d]) * cos(theta[d]*n)
// k'[n,64+d]  = silu(k[n,d]) * sin(theta[d]*n)
// ---------------------------------------------------------------------------
__global__ __launch_bounds__(256)
void kv_kernel(const float* __restrict__ theta)
{
    const int bh = blockIdx.x;          // 0..31
    const int b = bh >> 4, h = bh & 15;
    const int chunk = blockIdx.y;       // 0..7
    const int tid = threadIdx.x;

    __shared__ float skq[16][128];
    __shared__ float sv[16][64];

    const int ddg = (tid >> 4) * 8;     // dd block 0..120
    const int eg = (tid & 15) * 4;      // e block 0..60
    const float* base = g_qkvu + (size_t)b * Nn * 4096;
    const float* th = theta + h * DH;

    float acc[8][4];
#pragma unroll
    for (int i = 0; i < 8; i++)
#pragma unroll
        for (int j = 0; j < 4; j++) acc[i][j] = 0.f;

    for (int n0 = chunk * 256; n0 < chunk * 256 + 256; n0 += 16) {
        __syncthreads();
#pragma unroll
        for (int it = 0; it < 4; it++) {
            const int item = tid + it * 256;      // 0..1023
            const int nn = item >> 6;
            const int d = item & 63;
            const int n = n0 + nn;
            const float kraw = base[(size_t)n * 4096 + Dd + h * DH + d];
            const float s = silu_f(kraw);
            float sn, cs;
            sincosf(th[d] * (float)n, &sn, &cs);
            skq[nn][d] = s * cs;
            skq[nn][DH + d] = s * sn;
            sv[nn][d] = base[(size_t)n * 4096 + 2 * Dd + h * DH + d];
        }
        __syncthreads();
#pragma unroll
        for (int nn = 0; nn < 16; nn++) {
            float a[8], v[4];
            *(float4*)&a[0] = *(const float4*)&skq[nn][ddg];
            *(float4*)&a[4] = *(const float4*)&skq[nn][ddg + 4];
            *(float4*)&v[0] = *(const float4*)&sv[nn][eg];
#pragma unroll
            for (int i = 0; i < 8; i++)
#pragma unroll
                for (int j = 0; j < 4; j++)
                    acc[i][j] = fmaf(a[i], v[j], acc[i][j]);
        }
    }

    float* outp = g_kvp + (size_t)chunk * (32 * 8192) + (size_t)bh * 8192;
#pragma unroll
    for (int i = 0; i < 8; i++)
#pragma unroll
        for (int j = 0; j < 4; j++)
            outp[(ddg + i) * 64 + eg + j] = acc[i][j];
}

__global__ __launch_bounds__(256)
void kv_reduce()
{
    const int i = blockIdx.x * 256 + threadIdx.x;   // 0..262143
    float s = 0.f;
#pragma unroll
    for (int c = 0; c < 8; c++)
        s += g_kvp[(size_t)c * (32 * 8192) + i];
    g_kv[i] = s;
}

// ---------------------------------------------------------------------------
// attn[b,n,h*64+e] = sum_dd q'[n,dd] * KV[bh][dd][e]
// 32 tokens per block; KV cached in smem.
// ---------------------------------------------------------------------------
__global__ __launch_bounds__(256)
void qout_kernel(const float* __restrict__ theta)
{
    const int bh = blockIdx.x;
    const int b = bh >> 4, h = bh & 15;
    const int n0 = blockIdx.y * 32;
    const int tid = threadIdx.x;

    __shared__ float sKV[128][64];   // 32 KB
    __shared__ float sq[32][128];    // 16 KB

    const float* kvp = g_kv + (size_t)bh * 8192;
    for (int i = tid; i < 2048; i += 256)
        ((float4*)sKV)[i] = ((const float4*)kvp)[i];

    const float* base = g_qkvu + (size_t)b * Nn * 4096;
    const float* th = theta + h * DH;
#pragma unroll
    for (int it = 0; it < 8; it++) {
        const int item = tid + it * 256;       // 0..2047
        const int r = item >> 6;
        const int d = item & 63;
        const int n = n0 + r;
        const float x = base[(size_t)n * 4096 + h * DH + d];  // q block
        const float s = silu_f(x);
        float sn, cs;
        sincosf(th[d] * (float)n, &sn, &cs);
        sq[r][d] = s * cs;
        sq[r][DH + d] = s * sn;
    }
    __syncthreads();

    const int r = tid >> 3;            // 0..31
    const int e0 = (tid & 7) * 8;      // 0..56
    float acc[8];
#pragma unroll
    for (int j = 0; j < 8; j++) acc[j] = 0.f;

#pragma unroll 8
    for (int dd = 0; dd < 128; dd++) {
        const float a = sq[r][dd];
        float k[8];
        *(float4*)&k[0] = *(const float4*)&sKV[dd][e0];
        *(float4*)&k[4] = *(const float4*)&sKV[dd][e0 + 4];
#pragma unroll
        for (int j = 0; j < 8; j++)
            acc[j] = fmaf(a, k[j], acc[j]);
    }

    float* outp = g_attn + ((size_t)b * Nn + n0 + r) * Dd + h * DH + e0;
    *(float4*)&outp[0] = *(float4*)&acc[0];
    *(float4*)&outp[4] = *(float4*)&acc[4];
}

// ---------------------------------------------------------------------------
// LayerNorm over D + multiply by u
// ---------------------------------------------------------------------------
__device__ __forceinline__ float block_reduce_256(float v, float* sred, int tid)
{
#pragma unroll
    for (int o = 16; o; o >>= 1) v += __shfl_xor_sync(0xffffffffu, v, o);
    if ((tid & 31) == 0) sred[tid >> 5] = v;
    __syncthreads();
    float r;
    if (tid < 32) {
        float t = (tid < 8) ? sred[tid] : 0.f;
#pragma unroll
        for (int o = 4; o; o >>= 1) t += __shfl_xor_sync(0xffffffffu, t, o);
        if (tid == 0) sred[0] = t;
    }
    __syncthreads();
    r = sred[0];
    __syncthreads();
    return r;
}

__global__ __launch_bounds__(256)
void ln_kernel(const float* __restrict__ ln_w, const float* __restrict__ ln_b)
{
    __shared__ float sred[8];
    const int row = blockIdx.x;       // 0..4095
    const int tid = threadIdx.x;
    const int b = row >> 11, n = row & 2047;

    const float4 v = ((const float4*)(g_attn + (size_t)row * Dd))[tid];
    float s = v.x + v.y + v.z + v.w;
    const float mu = block_reduce_256(s, sred, tid) * (1.f / 1024.f);

    const float dx = v.x - mu, dy = v.y - mu, dz = v.z - mu, dw = v.w - mu;
    float s2 = dx * dx + dy * dy + dz * dz + dw * dw;
    const float var = block_reduce_256(s2, sred, tid) * (1.f / 1024.f);
    const float rstd = rsqrtf(var + 1e-5f);

    const float4 w4 = ((const float4*)ln_w)[tid];
    const float4 b4 = ((const float4*)ln_b)[tid];
    const float4 u4 = ((const float4*)(g_qkvu + ((size_t)b * Nn + n) * 4096 + 3 * Dd))[tid];

    float4 o;
    o.x = (dx * rstd * w4.x + b4.x) * u4.x;
    o.y = (dy * rstd * w4.y + b4.y) * u4.y;
    o.z = (dz * rstd * w4.z + b4.z) * u4.z;
    o.w = (dw * rstd * w4.w + b4.w) * u4.w;
    ((float4*)(g_norm + (size_t)row * Dd))[tid] = o;
}

// ---------------------------------------------------------------------------
extern "C" void kernel_launch(void* const* d_in, const int* in_sizes, int n_in,
                              void* d_out, int out_size)
{
    const float* x     = (const float*)d_in[0];
    // d_in[1] = context (unused by reference)
    const float* Wqkvu = (const float*)d_in[2];
    const float* bqkvu = (const float*)d_in[3];
    const float* Wout  = (const float*)d_in[4];
    const float* bout  = (const float*)d_in[5];
    const float* theta = (const float*)d_in[6];
    const float* ln_w  = (const float*)d_in[7];
    const float* ln_b  = (const float*)d_in[8];
    float* out = (float*)d_out;

    float *qkvu_p, *norm_p;
    cudaGetSymbolAddress((void**)&qkvu_p, g_qkvu);
    cudaGetSymbolAddress((void**)&norm_p, g_norm);

    // 1. qkvu = x @ Wqkvu^T + bqkvu   [4096 x 4096]
    {
        dim3 grid(4096 / 128, MROWS / 128);
        sgemm_nt<<<grid, 256>>>(x, Wqkvu, bqkvu, qkvu_p, MROWS, 4096, 1024);
    }
    // 2-3. KV = k'^T v  (partials then deterministic reduce)
    {
        dim3 grid(32, 8);
        kv_kernel<<<grid, 256>>>(theta);
        kv_reduce<<<1024, 256>>>();
    }
    // 4. attn = q' @ KV
    {
        dim3 grid(32, Nn / 32);
        qout_kernel<<<grid, 256>>>(theta);
    }
    // 5. LayerNorm + *u
    ln_kernel<<<MROWS, 256>>>(ln_w, ln_b);

    // 6. out = norm @ Wout^T + bout   [4096 x 1024]
    {
        dim3 grid(1024 / 128, MROWS / 128);
        sgemm_nt<<<grid, 256>>>(norm_p, Wout, bout, out, MROWS, 1024, 1024);
    }
}

// round 2
// speedup vs baseline: 2.2610x; 2.2610x over previous
#include <cuda_runtime.h>
#include <cstdint>
#include <math.h>

// ---------------------------------------------------------------------------
// NormLinearAttention  B=2 N=2048 D=1024 H=16 DH=64
// Right-form linear attention: out = q' @ (k'^T v)
// R1: TF32 tensor-core GEMMs (mma.sync m16n8k8) + cp.async double buffering;
//     qout rewritten with transposed q-smem (conflict-free) and 16 cols/thread.
// ---------------------------------------------------------------------------

#define Bb 2
#define Nn 2048
#define Dd 1024
#define Hh 16
#define DH 64
#define MROWS (Bb*Nn)        // 4096

// scratch (no dynamic allocation allowed)
__device__ float g_qkvu[(size_t)MROWS * 4 * Dd];     // 64 MB
__device__ float g_kvp[8 * 32 * 128 * 64];            // 8 MB partial KV
__device__ float g_kv[32 * 128 * 64];                 // 1 MB reduced KV
__device__ float g_attn[(size_t)MROWS * Dd];          // 16 MB
__device__ float g_norm[(size_t)MROWS * Dd];          // 16 MB

// ---------------------------------------------------------------------------
// TF32 helpers
// ---------------------------------------------------------------------------
__device__ __forceinline__ uint32_t f2tf32(float x) {
    uint32_t r;
    asm("cvt.rna.tf32.f32 %0, %1;" : "=r"(r) : "f"(x));
    return r;
}

__device__ __forceinline__ void mma_tf32(float* c, const uint32_t* a, const uint32_t* b) {
    asm volatile(
        "mma.sync.aligned.m16n8k8.row.col.f32.tf32.tf32.f32 "
        "{%0,%1,%2,%3}, {%4,%5,%6,%7}, {%8,%9}, {%0,%1,%2,%3};"
        : "+f"(c[0]), "+f"(c[1]), "+f"(c[2]), "+f"(c[3])
        : "r"(a[0]), "r"(a[1]), "r"(a[2]), "r"(a[3]), "r"(b[0]), "r"(b[1]));
}

__device__ __forceinline__ void cpa16(uint32_t dst, const float* src) {
    asm volatile("cp.async.cg.shared.global [%0], [%1], 16;" :: "r"(dst), "l"(src));
}
__device__ __forceinline__ void cpa_commit() {
    asm volatile("cp.async.commit_group;");
}
__device__ __forceinline__ void cpa_wait0() {
    asm volatile("cp.async.wait_group 0;");
}

// ---------------------------------------------------------------------------
// TF32 GEMM:  C[m,n] = sum_k A[m,k]*B[n,k] + bias[n]   (NT, both row-major)
// Block 128x128, BK=16, 256 threads (8 warps, warp tile 64x32),
// cp.async double-buffered smem, stride-20 padding (conflict-free frags).
// ---------------------------------------------------------------------------
#define BKt 16
#define SSTR 20   // smem row stride in floats

__global__ __launch_bounds__(256, 2)
void tgemm_nt(const float* __restrict__ A, const float* __restrict__ B,
              const float* __restrict__ bias, float* __restrict__ C,
              int M, int N, int K)
{
    __shared__ float sA[2][128 * SSTR];
    __shared__ float sB[2][128 * SSTR];

    const int tid = threadIdx.x;
    const int bm = blockIdx.y * 128;
    const int bn = blockIdx.x * 128;
    const int wid = tid >> 5, lane = tid & 31;
    const int g = lane >> 2, tg = lane & 3;
    const int wm = (wid >> 2) * 64;      // 0 or 64
    const int wn = (wid & 3) * 32;       // 0,32,64,96

    float acc[4][4][4];
#pragma unroll
    for (int mi = 0; mi < 4; mi++)
#pragma unroll
        for (int ni = 0; ni < 4; ni++)
#pragma unroll
            for (int j = 0; j < 4; j++) acc[mi][ni][j] = 0.f;

    // global load mapping: tile is 128 rows x 16 k = 512 float4; 2 per thread
    const int lrow = tid >> 2;           // 0..63  (rows lrow and lrow+64)
    const int lk = (tid & 3) * 4;        // 0,4,8,12
    const float* Ag = A + (size_t)(bm + lrow) * K + lk;
    const float* Bg = B + (size_t)(bn + lrow) * K + lk;

    uint32_t sAu = (uint32_t)__cvta_generic_to_shared(&sA[0][0]);
    uint32_t sBu = (uint32_t)__cvta_generic_to_shared(&sB[0][0]);
    const uint32_t dA0 = (lrow * SSTR + lk) * 4;
    const uint32_t dA1 = ((lrow + 64) * SSTR + lk) * 4;
    const uint32_t bufbytes = 128 * SSTR * 4;

    const int nt = K / BKt;

    // prologue: prefetch tile 0 into buf 0
    cpa16(sAu + dA0, Ag);
    cpa16(sAu + dA1, Ag + (size_t)64 * K);
    cpa16(sBu + dA0, Bg);
    cpa16(sBu + dA1, Bg + (size_t)64 * K);
    cpa_commit();

    int buf = 0;
    for (int kt = 0; kt < nt; kt++) {
        cpa_wait0();
        __syncthreads();

        if (kt + 1 < nt) {
            const int koff = (kt + 1) * BKt;
            const uint32_t so = (buf ^ 1) * bufbytes;
            cpa16(sAu + so + dA0, Ag + koff);
            cpa16(sAu + so + dA1, Ag + (size_t)64 * K + koff);
            cpa16(sBu + so + dA0, Bg + koff);
            cpa16(sBu + so + dA1, Bg + (size_t)64 * K + koff);
            cpa_commit();
        }

        const float* a_s = sA[buf];
        const float* b_s = sB[buf];
#pragma unroll
        for (int ks = 0; ks < 2; ks++) {
            const int k0 = ks * 8;
            uint32_t af[4][4], bf[4][2];
#pragma unroll
            for (int mi = 0; mi < 4; mi++) {
                const int r0 = wm + mi * 16 + g;
                af[mi][0] = f2tf32(a_s[r0 * SSTR + k0 + tg]);
                af[mi][1] = f2tf32(a_s[(r0 + 8) * SSTR + k0 + tg]);
                af[mi][2] = f2tf32(a_s[r0 * SSTR + k0 + tg + 4]);
                af[mi][3] = f2tf32(a_s[(r0 + 8) * SSTR + k0 + tg + 4]);
            }
#pragma unroll
            for (int ni = 0; ni < 4; ni++) {
                const int c0 = wn + ni * 8 + g;
                bf[ni][0] = f2tf32(b_s[c0 * SSTR + k0 + tg]);
                bf[ni][1] = f2tf32(b_s[c0 * SSTR + k0 + tg + 4]);
            }
#pragma unroll
            for (int mi = 0; mi < 4; mi++)
#pragma unroll
                for (int ni = 0; ni < 4; ni++)
                    mma_tf32(acc[mi][ni], af[mi], bf[ni]);
        }
        buf ^= 1;
    }

    // epilogue
#pragma unroll
    for (int mi = 0; mi < 4; mi++) {
        const int row = bm + wm + mi * 16 + g;
#pragma unroll
        for (int ni = 0; ni < 4; ni++) {
            const int col = bn + wn + ni * 8 + 2 * tg;
            const float bx = bias[col], by = bias[col + 1];
            float2 v0 = make_float2(acc[mi][ni][0] + bx, acc[mi][ni][1] + by);
            float2 v1 = make_float2(acc[mi][ni][2] + bx, acc[mi][ni][3] + by);
            *(float2*)&C[(size_t)row * N + col] = v0;
            *(float2*)&C[(size_t)(row + 8) * N + col] = v1;
        }
    }
}

__device__ __forceinline__ float silu_f(float x) {
    return x / (1.f + expf(-x));
}

// ---------------------------------------------------------------------------
// Partial KV: for (b,h), chunk of 256 tokens -> KV_part[128][64]
// ---------------------------------------------------------------------------
__global__ __launch_bounds__(256)
void kv_kernel(const float* __restrict__ theta)
{
    const int bh = blockIdx.x;          // 0..31
    const int b = bh >> 4, h = bh & 15;
    const int chunk = blockIdx.y;       // 0..7
    const int tid = threadIdx.x;

    __shared__ float skq[16][128];
    __shared__ float sv[16][64];

    const int ddg = (tid >> 4) * 8;
    const int eg = (tid & 15) * 4;
    const float* base = g_qkvu + (size_t)b * Nn * 4096;
    const float* th = theta + h * DH;

    float acc[8][4];
#pragma unroll
    for (int i = 0; i < 8; i++)
#pragma unroll
        for (int j = 0; j < 4; j++) acc[i][j] = 0.f;

    for (int n0 = chunk * 256; n0 < chunk * 256 + 256; n0 += 16) {
        __syncthreads();
#pragma unroll
        for (int it = 0; it < 4; it++) {
            const int item = tid + it * 256;
            const int nn = item >> 6;
            const int d = item & 63;
            const int n = n0 + nn;
            const float kraw = base[(size_t)n * 4096 + Dd + h * DH + d];
            const float s = silu_f(kraw);
            float sn, cs;
            sincosf(th[d] * (float)n, &sn, &cs);
            skq[nn][d] = s * cs;
            skq[nn][DH + d] = s * sn;
            sv[nn][d] = base[(size_t)n * 4096 + 2 * Dd + h * DH + d];
        }
        __syncthreads();
#pragma unroll
        for (int nn = 0; nn < 16; nn++) {
            float a[8], v[4];
            *(float4*)&a[0] = *(const float4*)&skq[nn][ddg];
            *(float4*)&a[4] = *(const float4*)&skq[nn][ddg + 4];
            *(float4*)&v[0] = *(const float4*)&sv[nn][eg];
#pragma unroll
            for (int i = 0; i < 8; i++)
#pragma unroll
                for (int j = 0; j < 4; j++)
                    acc[i][j] = fmaf(a[i], v[j], acc[i][j]);
        }
    }

    float* outp = g_kvp + (size_t)chunk * (32 * 8192) + (size_t)bh * 8192;
#pragma unroll
    for (int i = 0; i < 8; i++)
#pragma unroll
        for (int j = 0; j < 4; j++)
            outp[(ddg + i) * 64 + eg + j] = acc[i][j];
}

__global__ __launch_bounds__(256)
void kv_reduce()
{
    const int i = blockIdx.x * 256 + threadIdx.x;
    float s = 0.f;
#pragma unroll
    for (int c = 0; c < 8; c++)
        s += g_kvp[(size_t)c * (32 * 8192) + i];
    g_kv[i] = s;
}

// ---------------------------------------------------------------------------
// attn[b,n,h*64+e] = sum_dd q'[n,dd] * KV[bh][dd][e]
// 128 threads, 32 tokens/block; sq stored transposed [dd][r] (conflict-free
// reads); each thread computes 1 row x 16 cols.
// ---------------------------------------------------------------------------
__global__ __launch_bounds__(128)
void qout_kernel(const float* __restrict__ theta)
{
    const int bh = blockIdx.x;
    const int b = bh >> 4, h = bh & 15;
    const int n0 = blockIdx.y * 32;
    const int tid = threadIdx.x;
    const int w = tid >> 5, lane = tid & 31;

    __shared__ float sKV[128][64];   // 32 KB
    __shared__ float sq[128][32];    // 16 KB, transposed: [dd][token]

    const float* kvp = g_kv + (size_t)bh * 8192;
    for (int i = tid; i < 2048; i += 128)
        ((float4*)sKV)[i] = ((const float4*)kvp)[i];

    // fill sq: warp w handles d = w + 4*it, lane = token r (conflict-free STS)
    const float* base = g_qkvu + (size_t)b * Nn * 4096;
    const float* th = theta + h * DH;
    const int n = n0 + lane;
    const float* qrow = base + (size_t)n * 4096 + h * DH;
#pragma unroll
    for (int it = 0; it < 16; it++) {
        const int d = w + it * 4;
        const float s = silu_f(qrow[d]);
        float sn, cs;
        sincosf(th[d] * (float)n, &sn, &cs);
        sq[d][lane] = s * cs;
        sq[DH + d][lane] = s * sn;
    }
    __syncthreads();

    const int r = tid >> 2;            // 0..31
    const int e0 = (tid & 3) * 16;     // 0,16,32,48
    float acc[16];
#pragma unroll
    for (int j = 0; j < 16; j++) acc[j] = 0.f;

#pragma unroll 4
    for (int dd = 0; dd < 128; dd++) {
        const float a = sq[dd][r];
        float k[16];
        *(float4*)&k[0]  = *(const float4*)&sKV[dd][e0];
        *(float4*)&k[4]  = *(const float4*)&sKV[dd][e0 + 4];
        *(float4*)&k[8]  = *(const float4*)&sKV[dd][e0 + 8];
        *(float4*)&k[12] = *(const float4*)&sKV[dd][e0 + 12];
#pragma unroll
        for (int j = 0; j < 16; j++)
            acc[j] = fmaf(a, k[j], acc[j]);
    }

    float* outp = g_attn + ((size_t)b * Nn + n0 + r) * Dd + h * DH + e0;
    *(float4*)&outp[0]  = *(float4*)&acc[0];
    *(float4*)&outp[4]  = *(float4*)&acc[4];
    *(float4*)&outp[8]  = *(float4*)&acc[8];
    *(float4*)&outp[12] = *(float4*)&acc[12];
}

// ---------------------------------------------------------------------------
// LayerNorm over D + multiply by u
// ---------------------------------------------------------------------------
__device__ __forceinline__ float block_reduce_256(float v, float* sred, int tid)
{
#pragma unroll
    for (int o = 16; o; o >>= 1) v += __shfl_xor_sync(0xffffffffu, v, o);
    if ((tid & 31) == 0) sred[tid >> 5] = v;
    __syncthreads();
    float r;
    if (tid < 32) {
        float t = (tid < 8) ? sred[tid] : 0.f;
#pragma unroll
        for (int o = 4; o; o >>= 1) t += __shfl_xor_sync(0xffffffffu, t, o);
        if (tid == 0) sred[0] = t;
    }
    __syncthreads();
    r = sred[0];
    __syncthreads();
    return r;
}

__global__ __launch_bounds__(256)
void ln_kernel(const float* __restrict__ ln_w, const float* __restrict__ ln_b)
{
    __shared__ float sred[8];
    const int row = blockIdx.x;
    const int tid = threadIdx.x;
    const int b = row >> 11, n = row & 2047;

    const float4 v = ((const float4*)(g_attn + (size_t)row * Dd))[tid];
    float s = v.x + v.y + v.z + v.w;
    const float mu = block_reduce_256(s, sred, tid) * (1.f / 1024.f);

    const float dx = v.x - mu, dy = v.y - mu, dz = v.z - mu, dw = v.w - mu;
    float s2 = dx * dx + dy * dy + dz * dz + dw * dw;
    const float var = block_reduce_256(s2, sred, tid) * (1.f / 1024.f);
    const float rstd = rsqrtf(var + 1e-5f);

    const float4 w4 = ((const float4*)ln_w)[tid];
    const float4 b4 = ((const float4*)ln_b)[tid];
    const float4 u4 = ((const float4*)(g_qkvu + ((size_t)b * Nn + n) * 4096 + 3 * Dd))[tid];

    float4 o;
    o.x = (dx * rstd * w4.x + b4.x) * u4.x;
    o.y = (dy * rstd * w4.y + b4.y) * u4.y;
    o.z = (dz * rstd * w4.z + b4.z) * u4.z;
    o.w = (dw * rstd * w4.w + b4.w) * u4.w;
    ((float4*)(g_norm + (size_t)row * Dd))[tid] = o;
}

// ---------------------------------------------------------------------------
extern "C" void kernel_launch(void* const* d_in, const int* in_sizes, int n_in,
                              void* d_out, int out_size)
{
    const float* x     = (const float*)d_in[0];
    // d_in[1] = context (unused by reference)
    const float* Wqkvu = (const float*)d_in[2];
    const float* bqkvu = (const float*)d_in[3];
    const float* Wout  = (const float*)d_in[4];
    const float* bout  = (const float*)d_in[5];
    const float* theta = (const float*)d_in[6];
    const float* ln_w  = (const float*)d_in[7];
    const float* ln_b  = (const float*)d_in[8];
    float* out = (float*)d_out;

    float *qkvu_p, *norm_p;
    cudaGetSymbolAddress((void**)&qkvu_p, g_qkvu);
    cudaGetSymbolAddress((void**)&norm_p, g_norm);

    // 1. qkvu = x @ Wqkvu^T + bqkvu   [4096 x 4096]
    {
        dim3 grid(4096 / 128, MROWS / 128);
        tgemm_nt<<<grid, 256>>>(x, Wqkvu, bqkvu, qkvu_p, MROWS, 4096, 1024);
    }
    // 2-3. KV = k'^T v  (partials then deterministic reduce)
    {
        dim3 grid(32, 8);
        kv_kernel<<<grid, 256>>>(theta);
        kv_reduce<<<1024, 256>>>();
    }
    // 4. attn = q' @ KV
    {
        dim3 grid(32, Nn / 32);
        qout_kernel<<<grid, 128>>>(theta);
    }
    // 5. LayerNorm + *u
    ln_kernel<<<MROWS, 256>>>(ln_w, ln_b);

    // 6. out = norm @ Wout^T + bout   [4096 x 1024]
    {
        dim3 grid(1024 / 128, MROWS / 128);
        tgemm_nt<<<grid, 256>>>(norm_p, Wout, bout, out, MROWS, 1024, 1024);
    }
}

// round 3
// speedup vs baseline: 2.4971x; 1.1044x over previous
#include <cuda_runtime.h>
#include <cstdint>
#include <math.h>

// ---------------------------------------------------------------------------
// NormLinearAttention  B=2 N=2048 D=1024 H=16 DH=64
// Right-form linear attention: out = q' @ (k'^T v)
// R2: qout on tensor cores (mma.tf32), precomputed sin/cos table,
//     transposed KV for free col-major B operand.
// ---------------------------------------------------------------------------

#define Bb 2
#define Nn 2048
#define Dd 1024
#define Hh 16
#define DH 64
#define MROWS (Bb*Nn)        // 4096

// scratch (no dynamic allocation allowed)
__device__ float g_qkvu[(size_t)MROWS * 4 * Dd];     // 64 MB
__device__ float g_kvp[8 * 32 * 64 * 128];            // 8 MB partial KV (transposed [e][dd])
__device__ float g_kvT[32 * 64 * 128];                // 1 MB reduced KV^T [bh][e][dd]
__device__ float g_attn[(size_t)MROWS * Dd];          // 16 MB
__device__ float g_norm[(size_t)MROWS * Dd];          // 16 MB
__device__ float2 g_trig[(size_t)Hh * Nn * DH];       // 16 MB (cos,sin)

// ---------------------------------------------------------------------------
// TF32 helpers
// ---------------------------------------------------------------------------
__device__ __forceinline__ uint32_t f2tf32(float x) {
    uint32_t r;
    asm("cvt.rna.tf32.f32 %0, %1;" : "=r"(r) : "f"(x));
    return r;
}

__device__ __forceinline__ void mma_tf32(float* c, const uint32_t* a, const uint32_t* b) {
    asm volatile(
        "mma.sync.aligned.m16n8k8.row.col.f32.tf32.tf32.f32 "
        "{%0,%1,%2,%3}, {%4,%5,%6,%7}, {%8,%9}, {%0,%1,%2,%3};"
        : "+f"(c[0]), "+f"(c[1]), "+f"(c[2]), "+f"(c[3])
        : "r"(a[0]), "r"(a[1]), "r"(a[2]), "r"(a[3]), "r"(b[0]), "r"(b[1]));
}

__device__ __forceinline__ void cpa16(uint32_t dst, const float* src) {
    asm volatile("cp.async.cg.shared.global [%0], [%1], 16;" :: "r"(dst), "l"(src));
}
__device__ __forceinline__ void cpa_commit() {
    asm volatile("cp.async.commit_group;");
}
__device__ __forceinline__ void cpa_wait0() {
    asm volatile("cp.async.wait_group 0;");
}

// ---------------------------------------------------------------------------
// TF32 GEMM:  C[m,n] = sum_k A[m,k]*B[n,k] + bias[n]   (NT, both row-major)
// (validated in R1)
// ---------------------------------------------------------------------------
#define BKt 16
#define SSTR 20   // smem row stride in floats

__global__ __launch_bounds__(256, 2)
void tgemm_nt(const float* __restrict__ A, const float* __restrict__ B,
              const float* __restrict__ bias, float* __restrict__ C,
              int M, int N, int K)
{
    __shared__ float sA[2][128 * SSTR];
    __shared__ float sB[2][128 * SSTR];

    const int tid = threadIdx.x;
    const int bm = blockIdx.y * 128;
    const int bn = blockIdx.x * 128;
    const int wid = tid >> 5, lane = tid & 31;
    const int g = lane >> 2, tg = lane & 3;
    const int wm = (wid >> 2) * 64;      // 0 or 64
    const int wn = (wid & 3) * 32;       // 0,32,64,96

    float acc[4][4][4];
#pragma unroll
    for (int mi = 0; mi < 4; mi++)
#pragma unroll
        for (int ni = 0; ni < 4; ni++)
#pragma unroll
            for (int j = 0; j < 4; j++) acc[mi][ni][j] = 0.f;

    const int lrow = tid >> 2;
    const int lk = (tid & 3) * 4;
    const float* Ag = A + (size_t)(bm + lrow) * K + lk;
    const float* Bg = B + (size_t)(bn + lrow) * K + lk;

    uint32_t sAu = (uint32_t)__cvta_generic_to_shared(&sA[0][0]);
    uint32_t sBu = (uint32_t)__cvta_generic_to_shared(&sB[0][0]);
    const uint32_t dA0 = (lrow * SSTR + lk) * 4;
    const uint32_t dA1 = ((lrow + 64) * SSTR + lk) * 4;
    const uint32_t bufbytes = 128 * SSTR * 4;

    const int nt = K / BKt;

    cpa16(sAu + dA0, Ag);
    cpa16(sAu + dA1, Ag + (size_t)64 * K);
    cpa16(sBu + dA0, Bg);
    cpa16(sBu + dA1, Bg + (size_t)64 * K);
    cpa_commit();

    int buf = 0;
    for (int kt = 0; kt < nt; kt++) {
        cpa_wait0();
        __syncthreads();

        if (kt + 1 < nt) {
            const int koff = (kt + 1) * BKt;
            const uint32_t so = (buf ^ 1) * bufbytes;
            cpa16(sAu + so + dA0, Ag + koff);
            cpa16(sAu + so + dA1, Ag + (size_t)64 * K + koff);
            cpa16(sBu + so + dA0, Bg + koff);
            cpa16(sBu + so + dA1, Bg + (size_t)64 * K + koff);
            cpa_commit();
        }

        const float* a_s = sA[buf];
        const float* b_s = sB[buf];
#pragma unroll
        for (int ks = 0; ks < 2; ks++) {
            const int k0 = ks * 8;
            uint32_t af[4][4], bf[4][2];
#pragma unroll
            for (int mi = 0; mi < 4; mi++) {
                const int r0 = wm + mi * 16 + g;
                af[mi][0] = f2tf32(a_s[r0 * SSTR + k0 + tg]);
                af[mi][1] = f2tf32(a_s[(r0 + 8) * SSTR + k0 + tg]);
                af[mi][2] = f2tf32(a_s[r0 * SSTR + k0 + tg + 4]);
                af[mi][3] = f2tf32(a_s[(r0 + 8) * SSTR + k0 + tg + 4]);
            }
#pragma unroll
            for (int ni = 0; ni < 4; ni++) {
                const int c0 = wn + ni * 8 + g;
                bf[ni][0] = f2tf32(b_s[c0 * SSTR + k0 + tg]);
                bf[ni][1] = f2tf32(b_s[c0 * SSTR + k0 + tg + 4]);
            }
#pragma unroll
            for (int mi = 0; mi < 4; mi++)
#pragma unroll
                for (int ni = 0; ni < 4; ni++)
                    mma_tf32(acc[mi][ni], af[mi], bf[ni]);
        }
        buf ^= 1;
    }

#pragma unroll
    for (int mi = 0; mi < 4; mi++) {
        const int row = bm + wm + mi * 16 + g;
#pragma unroll
        for (int ni = 0; ni < 4; ni++) {
            const int col = bn + wn + ni * 8 + 2 * tg;
            const float bx = bias[col], by = bias[col + 1];
            float2 v0 = make_float2(acc[mi][ni][0] + bx, acc[mi][ni][1] + by);
            float2 v1 = make_float2(acc[mi][ni][2] + bx, acc[mi][ni][3] + by);
            *(float2*)&C[(size_t)row * N + col] = v0;
            *(float2*)&C[(size_t)(row + 8) * N + col] = v1;
        }
    }
}

__device__ __forceinline__ float silu_f(float x) {
    return x / (1.f + expf(-x));
}

// ---------------------------------------------------------------------------
// Trig table: g_trig[h][n][d] = (cos(theta*n), sin(theta*n))
// ---------------------------------------------------------------------------
__global__ __launch_bounds__(256)
void trig_kernel(const float* __restrict__ theta)
{
    const int idx = blockIdx.x * 256 + threadIdx.x;    // 0..2097151
    const int d = idx & 63;
    const int n = (idx >> 6) & 2047;
    const int h = idx >> 17;
    float sn, cs;
    sincosf(theta[h * DH + d] * (float)n, &sn, &cs);
    g_trig[idx] = make_float2(cs, sn);
}

// ---------------------------------------------------------------------------
// Partial KV: for (b,h), chunk of 256 tokens -> KV_part^T [e][dd] (64x128)
// ---------------------------------------------------------------------------
__global__ __launch_bounds__(256)
void kv_kernel()
{
    const int bh = blockIdx.x;          // 0..31
    const int b = bh >> 4, h = bh & 15;
    const int chunk = blockIdx.y;       // 0..7
    const int tid = threadIdx.x;

    __shared__ float skq[16][128];
    __shared__ float sv[16][64];

    const int ddg = (tid >> 4) * 8;
    const int eg = (tid & 15) * 4;
    const float* base = g_qkvu + (size_t)b * Nn * 4096;
    const float2* trig = g_trig + (size_t)h * Nn * DH;

    float acc[8][4];
#pragma unroll
    for (int i = 0; i < 8; i++)
#pragma unroll
        for (int j = 0; j < 4; j++) acc[i][j] = 0.f;

    for (int n0 = chunk * 256; n0 < chunk * 256 + 256; n0 += 16) {
        __syncthreads();
#pragma unroll
        for (int it = 0; it < 4; it++) {
            const int item = tid + it * 256;
            const int nn = item >> 6;
            const int d = item & 63;
            const int n = n0 + nn;
            const float kraw = base[(size_t)n * 4096 + Dd + h * DH + d];
            const float s = silu_f(kraw);
            const float2 t = trig[(size_t)n * DH + d];
            skq[nn][d] = s * t.x;
            skq[nn][DH + d] = s * t.y;
            sv[nn][d] = base[(size_t)n * 4096 + 2 * Dd + h * DH + d];
        }
        __syncthreads();
#pragma unroll
        for (int nn = 0; nn < 16; nn++) {
            float a[8], v[4];
            *(float4*)&a[0] = *(const float4*)&skq[nn][ddg];
            *(float4*)&a[4] = *(const float4*)&skq[nn][ddg + 4];
            *(float4*)&v[0] = *(const float4*)&sv[nn][eg];
#pragma unroll
            for (int i = 0; i < 8; i++)
#pragma unroll
                for (int j = 0; j < 4; j++)
                    acc[i][j] = fmaf(a[i], v[j], acc[i][j]);
        }
    }

    // write transposed: [e][dd]
    float* outp = g_kvp + (size_t)chunk * (32 * 8192) + (size_t)bh * 8192;
#pragma unroll
    for (int i = 0; i < 8; i++)
#pragma unroll
        for (int j = 0; j < 4; j++)
            outp[(eg + j) * 128 + ddg + i] = acc[i][j];
}

__global__ __launch_bounds__(256)
void kv_reduce()
{
    const int i = blockIdx.x * 256 + threadIdx.x;   // 0..262143
    float s = 0.f;
#pragma unroll
    for (int c = 0; c < 8; c++)
        s += g_kvp[(size_t)c * (32 * 8192) + i];
    g_kvT[i] = s;
}

// ---------------------------------------------------------------------------
// qout (tensor cores): per block: bh, 128-token tile.
// attn[tok, h*64+e] = sum_dd q'[tok,dd] * KVT[e,dd]
// smem: sQ[128][132] (A, row-major) + sKVt[64][132] (B, "col-major" = [n][k])
// 8 warps as 4(m) x 2(n); warp tile 32x32.
// ---------------------------------------------------------------------------
#define QSTR 132

__global__ __launch_bounds__(256)
void qout_kernel()
{
    extern __shared__ float qsm[];
    float* sQ = qsm;                     // 128 * 132
    float* sKVt = qsm + 128 * QSTR;      // 64 * 132

    const int bh = blockIdx.x;
    const int b = bh >> 4, h = bh & 15;
    const int n0 = blockIdx.y * 128;
    const int tid = threadIdx.x;
    const int wid = tid >> 5, lane = tid & 31;
    const int g = lane >> 2, tg = lane & 3;

    // load KV^T [64][128] -> sKVt
    {
        const float4* src = (const float4*)(g_kvT + (size_t)bh * 8192);
        for (int i = tid; i < 2048; i += 256) {
            const int e = i >> 5;
            const int dc = (i & 31) * 4;
            *(float4*)&sKVt[e * QSTR + dc] = src[i];
        }
    }

    // build q' for 128 tokens: thread handles token=tid>>1, d range of 32
    {
        const int token = tid >> 1;
        const int d0 = (tid & 1) * 32;
        const int n = n0 + token;
        const float* qrow = g_qkvu + ((size_t)b * Nn + n) * 4096 + h * DH + d0;
        const float2* trow = g_trig + ((size_t)h * Nn + n) * DH + d0;
        float* dst = sQ + token * QSTR;
#pragma unroll
        for (int d = 0; d < 32; d++) {
            const float s = silu_f(qrow[d]);
            const float2 t = trow[d];
            dst[d0 + d] = s * t.x;
            dst[DH + d0 + d] = s * t.y;
        }
    }
    __syncthreads();

    const int wm = (wid >> 1) * 32;      // 0,32,64,96
    const int wn = (wid & 1) * 32;       // 0,32

    float acc[2][4][4];
#pragma unroll
    for (int mi = 0; mi < 2; mi++)
#pragma unroll
        for (int ni = 0; ni < 4; ni++)
#pragma unroll
            for (int j = 0; j < 4; j++) acc[mi][ni][j] = 0.f;

#pragma unroll
    for (int k0 = 0; k0 < 128; k0 += 8) {
        uint32_t af[2][4], bf[4][2];
#pragma unroll
        for (int mi = 0; mi < 2; mi++) {
            const int r0 = wm + mi * 16 + g;
            af[mi][0] = f2tf32(sQ[r0 * QSTR + k0 + tg]);
            af[mi][1] = f2tf32(sQ[(r0 + 8) * QSTR + k0 + tg]);
            af[mi][2] = f2tf32(sQ[r0 * QSTR + k0 + tg + 4]);
            af[mi][3] = f2tf32(sQ[(r0 + 8) * QSTR + k0 + tg + 4]);
        }
#pragma unroll
        for (int ni = 0; ni < 4; ni++) {
            const int c0 = wn + ni * 8 + g;
            bf[ni][0] = f2tf32(sKVt[c0 * QSTR + k0 + tg]);
            bf[ni][1] = f2tf32(sKVt[c0 * QSTR + k0 + tg + 4]);
        }
#pragma unroll
        for (int mi = 0; mi < 2; mi++)
#pragma unroll
            for (int ni = 0; ni < 4; ni++)
                mma_tf32(acc[mi][ni], af[mi], bf[ni]);
    }

    // epilogue -> g_attn[b][n][h*64+e]
#pragma unroll
    for (int mi = 0; mi < 2; mi++) {
        const int row = n0 + wm + mi * 16 + g;
        float* base0 = g_attn + ((size_t)b * Nn + row) * Dd + h * DH;
        float* base1 = g_attn + ((size_t)b * Nn + row + 8) * Dd + h * DH;
#pragma unroll
        for (int ni = 0; ni < 4; ni++) {
            const int col = wn + ni * 8 + 2 * tg;
            *(float2*)&base0[col] = make_float2(acc[mi][ni][0], acc[mi][ni][1]);
            *(float2*)&base1[col] = make_float2(acc[mi][ni][2], acc[mi][ni][3]);
        }
    }
}

// ---------------------------------------------------------------------------
// LayerNorm over D + multiply by u
// ---------------------------------------------------------------------------
__device__ __forceinline__ float block_reduce_256(float v, float* sred, int tid)
{
#pragma unroll
    for (int o = 16; o; o >>= 1) v += __shfl_xor_sync(0xffffffffu, v, o);
    if ((tid & 31) == 0) sred[tid >> 5] = v;
    __syncthreads();
    float r;
    if (tid < 32) {
        float t = (tid < 8) ? sred[tid] : 0.f;
#pragma unroll
        for (int o = 4; o; o >>= 1) t += __shfl_xor_sync(0xffffffffu, t, o);
        if (tid == 0) sred[0] = t;
    }
    __syncthreads();
    r = sred[0];
    __syncthreads();
    return r;
}

__global__ __launch_bounds__(256)
void ln_kernel(const float* __restrict__ ln_w, const float* __restrict__ ln_b)
{
    __shared__ float sred[8];
    const int row = blockIdx.x;
    const int tid = threadIdx.x;
    const int b = row >> 11, n = row & 2047;

    const float4 v = ((const float4*)(g_attn + (size_t)row * Dd))[tid];
    float s = v.x + v.y + v.z + v.w;
    const float mu = block_reduce_256(s, sred, tid) * (1.f / 1024.f);

    const float dx = v.x - mu, dy = v.y - mu, dz = v.z - mu, dw = v.w - mu;
    float s2 = dx * dx + dy * dy + dz * dz + dw * dw;
    const float var = block_reduce_256(s2, sred, tid) * (1.f / 1024.f);
    const float rstd = rsqrtf(var + 1e-5f);

    const float4 w4 = ((const float4*)ln_w)[tid];
    const float4 b4 = ((const float4*)ln_b)[tid];
    const float4 u4 = ((const float4*)(g_qkvu + ((size_t)b * Nn + n) * 4096 + 3 * Dd))[tid];

    float4 o;
    o.x = (dx * rstd * w4.x + b4.x) * u4.x;
    o.y = (dy * rstd * w4.y + b4.y) * u4.y;
    o.z = (dz * rstd * w4.z + b4.z) * u4.z;
    o.w = (dw * rstd * w4.w + b4.w) * u4.w;
    ((float4*)(g_norm + (size_t)row * Dd))[tid] = o;
}

// ---------------------------------------------------------------------------
extern "C" void kernel_launch(void* const* d_in, const int* in_sizes, int n_in,
                              void* d_out, int out_size)
{
    const float* x     = (const float*)d_in[0];
    // d_in[1] = context (unused by reference)
    const float* Wqkvu = (const float*)d_in[2];
    const float* bqkvu = (const float*)d_in[3];
    const float* Wout  = (const float*)d_in[4];
    const float* bout  = (const float*)d_in[5];
    const float* theta = (const float*)d_in[6];
    const float* ln_w  = (const float*)d_in[7];
    const float* ln_b  = (const float*)d_in[8];
    float* out = (float*)d_out;

    float *qkvu_p, *norm_p;
    cudaGetSymbolAddress((void**)&qkvu_p, g_qkvu);
    cudaGetSymbolAddress((void**)&norm_p, g_norm);

    static bool attr_done = false;
    if (!attr_done) {
        cudaFuncSetAttribute(qout_kernel,
                             cudaFuncAttributeMaxDynamicSharedMemorySize,
                             (128 + 64) * QSTR * 4);
        attr_done = true;
    }

    // 0. trig table
    trig_kernel<<<(Hh * Nn * DH) / 256, 256>>>(theta);

    // 1. qkvu = x @ Wqkvu^T + bqkvu   [4096 x 4096]
    {
        dim3 grid(4096 / 128, MROWS / 128);
        tgemm_nt<<<grid, 256>>>(x, Wqkvu, bqkvu, qkvu_p, MROWS, 4096, 1024);
    }
    // 2-3. KV^T = (k'^T v)^T  (partials then deterministic reduce)
    {
        dim3 grid(32, 8);
        kv_kernel<<<grid, 256>>>();
        kv_reduce<<<1024, 256>>>();
    }
    // 4. attn = q' @ KV  (tensor cores)
    {
        dim3 grid(32, Nn / 128);
        qout_kernel<<<grid, 256, (128 + 64) * QSTR * 4>>>();
    }
    // 5. LayerNorm + *u
    ln_kernel<<<MROWS, 256>>>(ln_w, ln_b);

    // 6. out = norm @ Wout^T + bout   [4096 x 1024]
    {
        dim3 grid(1024 / 128, MROWS / 128);
        tgemm_nt<<<grid, 256>>>(norm_p, Wout, bout, out, MROWS, 1024, 1024);
    }
}

// round 8
// speedup vs baseline: 2.5768x; 1.0319x over previous
#include <cuda_runtime.h>
#include <cstdint>
#include <math.h>

// ---------------------------------------------------------------------------
// NormLinearAttention  B=2 N=2048 D=1024 H=16 DH=64
// Right-form linear attention: out = q' @ (k'^T v)
// R6 (= R4 resubmit after infra failure):
//   pre-rounded tf32 operands (no cvt in GEMM inner loops) +
//   3-stage cp.async pipeline in tgemm.
// ---------------------------------------------------------------------------

#define Bb 2
#define Nn 2048
#define Dd 1024
#define Hh 16
#define DH 64
#define MROWS (Bb*Nn)        // 4096

// scratch (no dynamic allocation allowed)
__device__ float g_qkvu[(size_t)MROWS * 4 * Dd];     // 64 MB
__device__ float g_kvp[8 * 32 * 64 * 128];            // 8 MB partial KV^T
__device__ float g_kvT[32 * 64 * 128];                // 1 MB reduced KV^T (tf32-rounded)
__device__ float g_attn[(size_t)MROWS * Dd];          // 16 MB
__device__ float g_norm[(size_t)MROWS * Dd];          // 16 MB (tf32-rounded)
__device__ float2 g_trig[(size_t)Hh * Nn * DH];       // 16 MB (cos,sin)
__device__ float g_xr[(size_t)MROWS * Dd];            // 16 MB x rounded
__device__ float g_wqr[(size_t)4 * Dd * Dd];          // 16 MB Wqkvu rounded
__device__ float g_wor[(size_t)Dd * Dd];              // 4 MB Wout rounded

// ---------------------------------------------------------------------------
// TF32 helpers
// ---------------------------------------------------------------------------
__device__ __forceinline__ uint32_t f2tf32(float x) {
    uint32_t r;
    asm("cvt.rna.tf32.f32 %0, %1;" : "=r"(r) : "f"(x));
    return r;
}
__device__ __forceinline__ float roundtf(float x) {
    return __uint_as_float(f2tf32(x));
}

__device__ __forceinline__ void mma_tf32(float* c, const uint32_t* a, const uint32_t* b) {
    asm volatile(
        "mma.sync.aligned.m16n8k8.row.col.f32.tf32.tf32.f32 "
        "{%0,%1,%2,%3}, {%4,%5,%6,%7}, {%8,%9}, {%0,%1,%2,%3};"
        : "+f"(c[0]), "+f"(c[1]), "+f"(c[2]), "+f"(c[3])
        : "r"(a[0]), "r"(a[1]), "r"(a[2]), "r"(a[3]), "r"(b[0]), "r"(b[1]));
}

__device__ __forceinline__ void cpa16(uint32_t dst, const float* src) {
    asm volatile("cp.async.cg.shared.global [%0], [%1], 16;" :: "r"(dst), "l"(src));
}
__device__ __forceinline__ void cpa_commit() {
    asm volatile("cp.async.commit_group;");
}
__device__ __forceinline__ void cpa_wait1() {
    asm volatile("cp.async.wait_group 1;");
}

// ---------------------------------------------------------------------------
// Pre-round fp32 -> tf32 (elementwise, float4)
// ---------------------------------------------------------------------------
__global__ __launch_bounds__(256)
void round_kernel(const float4* __restrict__ src, float4* __restrict__ dst, int n4)
{
    const int i = blockIdx.x * 256 + threadIdx.x;
    if (i < n4) {
        float4 v = src[i];
        v.x = roundtf(v.x); v.y = roundtf(v.y);
        v.z = roundtf(v.z); v.w = roundtf(v.w);
        dst[i] = v;
    }
}

// ---------------------------------------------------------------------------
// TF32 GEMM:  C[m,n] = sum_k A[m,k]*B[n,k] + bias[n]   (NT, both row-major)
// A,B must be tf32-pre-rounded. 128x128 tile, BK=16, 3-stage cp.async.
// ---------------------------------------------------------------------------
#define BKt 16
#define SSTR 20         // smem row stride in floats
#define STG_F (2 * 128 * SSTR)   // floats per stage (A then B)
#define TG_SMEM (3 * STG_F * 4)  // bytes

__global__ __launch_bounds__(256, 2)
void tgemm_nt(const float* __restrict__ A, const float* __restrict__ B,
              const float* __restrict__ bias, float* __restrict__ C,
              int M, int N, int K)
{
    extern __shared__ float smp[];

    const int tid = threadIdx.x;
    const int bm = blockIdx.y * 128;
    const int bn = blockIdx.x * 128;
    const int wid = tid >> 5, lane = tid & 31;
    const int g = lane >> 2, tg = lane & 3;
    const int wm = (wid >> 2) * 64;      // 0 or 64
    const int wn = (wid & 3) * 32;       // 0,32,64,96

    float acc[4][4][4];
#pragma unroll
    for (int mi = 0; mi < 4; mi++)
#pragma unroll
        for (int ni = 0; ni < 4; ni++)
#pragma unroll
            for (int j = 0; j < 4; j++) acc[mi][ni][j] = 0.f;

    const int lrow = tid >> 2;           // 0..63
    const int lk = (tid & 3) * 4;        // 0,4,8,12
    const float* Ag = A + (size_t)(bm + lrow) * K + lk;
    const float* Bg = B + (size_t)(bn + lrow) * K + lk;

    const uint32_t sbase = (uint32_t)__cvta_generic_to_shared(smp);
    const uint32_t dA0 = (lrow * SSTR + lk) * 4;
    const uint32_t dA1 = ((lrow + 64) * SSTR + lk) * 4;
    const uint32_t dB = 128 * SSTR * 4;
    const uint32_t stgb = STG_F * 4;

    const int nt = K / BKt;

    // prologue: prefetch kt=0,1 into stages 0,1
#pragma unroll
    for (int s = 0; s < 2; s++) {
        const int koff = s * BKt;
        const uint32_t so = sbase + s * stgb;
        cpa16(so + dA0, Ag + koff);
        cpa16(so + dA1, Ag + (size_t)64 * K + koff);
        cpa16(so + dB + dA0, Bg + koff);
        cpa16(so + dB + dA1, Bg + (size_t)64 * K + koff);
        cpa_commit();
    }

    int st = 0;
    for (int kt = 0; kt < nt; kt++) {
        cpa_wait1();
        __syncthreads();

        if (kt + 2 < nt) {
            const int koff = (kt + 2) * BKt;
            int sn = st + 2; if (sn >= 3) sn -= 3;
            const uint32_t so = sbase + sn * stgb;
            cpa16(so + dA0, Ag + koff);
            cpa16(so + dA1, Ag + (size_t)64 * K + koff);
            cpa16(so + dB + dA0, Bg + koff);
            cpa16(so + dB + dA1, Bg + (size_t)64 * K + koff);
            cpa_commit();
        }

        const float* a_s = smp + st * STG_F;
        const float* b_s = a_s + 128 * SSTR;
#pragma unroll
        for (int ks = 0; ks < 2; ks++) {
            const int k0 = ks * 8;
            uint32_t af[4][4], bf[4][2];
#pragma unroll
            for (int mi = 0; mi < 4; mi++) {
                const int r0 = wm + mi * 16 + g;
                af[mi][0] = __float_as_uint(a_s[r0 * SSTR + k0 + tg]);
                af[mi][1] = __float_as_uint(a_s[(r0 + 8) * SSTR + k0 + tg]);
                af[mi][2] = __float_as_uint(a_s[r0 * SSTR + k0 + tg + 4]);
                af[mi][3] = __float_as_uint(a_s[(r0 + 8) * SSTR + k0 + tg + 4]);
            }
#pragma unroll
            for (int ni = 0; ni < 4; ni++) {
                const int c0 = wn + ni * 8 + g;
                bf[ni][0] = __float_as_uint(b_s[c0 * SSTR + k0 + tg]);
                bf[ni][1] = __float_as_uint(b_s[c0 * SSTR + k0 + tg + 4]);
            }
#pragma unroll
            for (int mi = 0; mi < 4; mi++)
#pragma unroll
                for (int ni = 0; ni < 4; ni++)
                    mma_tf32(acc[mi][ni], af[mi], bf[ni]);
        }
        if (++st == 3) st = 0;
    }

#pragma unroll
    for (int mi = 0; mi < 4; mi++) {
        const int row = bm + wm + mi * 16 + g;
#pragma unroll
        for (int ni = 0; ni < 4; ni++) {
            const int col = bn + wn + ni * 8 + 2 * tg;
            const float bx = bias[col], by = bias[col + 1];
            float2 v0 = make_float2(acc[mi][ni][0] + bx, acc[mi][ni][1] + by);
            float2 v1 = make_float2(acc[mi][ni][2] + bx, acc[mi][ni][3] + by);
            *(float2*)&C[(size_t)row * N + col] = v0;
            *(float2*)&C[(size_t)(row + 8) * N + col] = v1;
        }
    }
}

__device__ __forceinline__ float silu_f(float x) {
    return x / (1.f + expf(-x));
}

// ---------------------------------------------------------------------------
// Trig table: g_trig[h][n][d] = (cos(theta*n), sin(theta*n))
// ---------------------------------------------------------------------------
__global__ __launch_bounds__(256)
void trig_kernel(const float* __restrict__ theta)
{
    const int idx = blockIdx.x * 256 + threadIdx.x;
    const int d = idx & 63;
    const int n = (idx >> 6) & 2047;
    const int h = idx >> 17;
    float sn, cs;
    sincosf(theta[h * DH + d] * (float)n, &sn, &cs);
    g_trig[idx] = make_float2(cs, sn);
}

// ---------------------------------------------------------------------------
// Partial KV: for (b,h), chunk of 256 tokens -> KV_part^T [e][dd] (64x128)
// ---------------------------------------------------------------------------
__global__ __launch_bounds__(256)
void kv_kernel()
{
    const int bh = blockIdx.x;
    const int b = bh >> 4, h = bh & 15;
    const int chunk = blockIdx.y;
    const int tid = threadIdx.x;

    __shared__ float skq[16][128];
    __shared__ float sv[16][64];

    const int ddg = (tid >> 4) * 8;
    const int eg = (tid & 15) * 4;
    const float* base = g_qkvu + (size_t)b * Nn * 4096;
    const float2* trig = g_trig + (size_t)h * Nn * DH;

    float acc[8][4];
#pragma unroll
    for (int i = 0; i < 8; i++)
#pragma unroll
        for (int j = 0; j < 4; j++) acc[i][j] = 0.f;

    for (int n0 = chunk * 256; n0 < chunk * 256 + 256; n0 += 16) {
        __syncthreads();
#pragma unroll
        for (int it = 0; it < 4; it++) {
            const int item = tid + it * 256;
            const int nn = item >> 6;
            const int d = item & 63;
            const int n = n0 + nn;
            const float kraw = base[(size_t)n * 4096 + Dd + h * DH + d];
            const float s = silu_f(kraw);
            const float2 t = trig[(size_t)n * DH + d];
            skq[nn][d] = s * t.x;
            skq[nn][DH + d] = s * t.y;
            sv[nn][d] = base[(size_t)n * 4096 + 2 * Dd + h * DH + d];
        }
        __syncthreads();
#pragma unroll
        for (int nn = 0; nn < 16; nn++) {
            float a[8], v[4];
            *(float4*)&a[0] = *(const float4*)&skq[nn][ddg];
            *(float4*)&a[4] = *(const float4*)&skq[nn][ddg + 4];
            *(float4*)&v[0] = *(const float4*)&sv[nn][eg];
#pragma unroll
            for (int i = 0; i < 8; i++)
#pragma unroll
                for (int j = 0; j < 4; j++)
                    acc[i][j] = fmaf(a[i], v[j], acc[i][j]);
        }
    }

    float* outp = g_kvp + (size_t)chunk * (32 * 8192) + (size_t)bh * 8192;
#pragma unroll
    for (int i = 0; i < 8; i++)
#pragma unroll
        for (int j = 0; j < 4; j++)
            outp[(eg + j) * 128 + ddg + i] = acc[i][j];
}

__global__ __launch_bounds__(256)
void kv_reduce()
{
    const int i = blockIdx.x * 256 + threadIdx.x;
    float s = 0.f;
#pragma unroll
    for (int c = 0; c < 8; c++)
        s += g_kvp[(size_t)c * (32 * 8192) + i];
    g_kvT[i] = roundtf(s);
}

// ---------------------------------------------------------------------------
// qout (tensor cores): per block: bh, 128-token tile.
// smem operands tf32-pre-rounded at fill time.
// ---------------------------------------------------------------------------
#define QSTR 132

__global__ __launch_bounds__(256)
void qout_kernel()
{
    extern __shared__ float qsm[];
    float* sQ = qsm;                     // 128 * 132
    float* sKVt = qsm + 128 * QSTR;      // 64 * 132

    const int bh = blockIdx.x;
    const int b = bh >> 4, h = bh & 15;
    const int n0 = blockIdx.y * 128;
    const int tid = threadIdx.x;
    const int wid = tid >> 5, lane = tid & 31;
    const int g = lane >> 2, tg = lane & 3;

    // load KV^T [64][128] -> sKVt (already rounded in kv_reduce)
    {
        const float4* src = (const float4*)(g_kvT + (size_t)bh * 8192);
        for (int i = tid; i < 2048; i += 256) {
            const int e = i >> 5;
            const int dc = (i & 31) * 4;
            *(float4*)&sKVt[e * QSTR + dc] = src[i];
        }
    }

    // build q' for 128 tokens (rounded at fill)
    {
        const int token = tid >> 1;
        const int d0 = (tid & 1) * 32;
        const int n = n0 + token;
        const float* qrow = g_qkvu + ((size_t)b * Nn + n) * 4096 + h * DH + d0;
        const float2* trow = g_trig + ((size_t)h * Nn + n) * DH + d0;
        float* dst = sQ + token * QSTR;
#pragma unroll
        for (int d = 0; d < 32; d++) {
            const float s = silu_f(qrow[d]);
            const float2 t = trow[d];
            dst[d0 + d] = roundtf(s * t.x);
            dst[DH + d0 + d] = roundtf(s * t.y);
        }
    }
    __syncthreads();

    const int wm = (wid >> 1) * 32;
    const int wn = (wid & 1) * 32;

    float acc[2][4][4];
#pragma unroll
    for (int mi = 0; mi < 2; mi++)
#pragma unroll
        for (int ni = 0; ni < 4; ni++)
#pragma unroll
            for (int j = 0; j < 4; j++) acc[mi][ni][j] = 0.f;

#pragma unroll
    for (int k0 = 0; k0 < 128; k0 += 8) {
        uint32_t af[2][4], bf[4][2];
#pragma unroll
        for (int mi = 0; mi < 2; mi++) {
            const int r0 = wm + mi * 16 + g;
            af[mi][0] = __float_as_uint(sQ[r0 * QSTR + k0 + tg]);
            af[mi][1] = __float_as_uint(sQ[(r0 + 8) * QSTR + k0 + tg]);
            af[mi][2] = __float_as_uint(sQ[r0 * QSTR + k0 + tg + 4]);
            af[mi][3] = __float_as_uint(sQ[(r0 + 8) * QSTR + k0 + tg + 4]);
        }
#pragma unroll
        for (int ni = 0; ni < 4; ni++) {
            const int c0 = wn + ni * 8 + g;
            bf[ni][0] = __float_as_uint(sKVt[c0 * QSTR + k0 + tg]);
            bf[ni][1] = __float_as_uint(sKVt[c0 * QSTR + k0 + tg + 4]);
        }
#pragma unroll
        for (int mi = 0; mi < 2; mi++)
#pragma unroll
            for (int ni = 0; ni < 4; ni++)
                mma_tf32(acc[mi][ni], af[mi], bf[ni]);
    }

#pragma unroll
    for (int mi = 0; mi < 2; mi++) {
        const int row = n0 + wm + mi * 16 + g;
        float* base0 = g_attn + ((size_t)b * Nn + row) * Dd + h * DH;
        float* base1 = g_attn + ((size_t)b * Nn + row + 8) * Dd + h * DH;
#pragma unroll
        for (int ni = 0; ni < 4; ni++) {
            const int col = wn + ni * 8 + 2 * tg;
            *(float2*)&base0[col] = make_float2(acc[mi][ni][0], acc[mi][ni][1]);
            *(float2*)&base1[col] = make_float2(acc[mi][ni][2], acc[mi][ni][3]);
        }
    }
}

// ---------------------------------------------------------------------------
// LayerNorm over D + multiply by u; output tf32-rounded for GEMM2
// ---------------------------------------------------------------------------
__device__ __forceinline__ float block_reduce_256(float v, float* sred, int tid)
{
#pragma unroll
    for (int o = 16; o; o >>= 1) v += __shfl_xor_sync(0xffffffffu, v, o);
    if ((tid & 31) == 0) sred[tid >> 5] = v;
    __syncthreads();
    float r;
    if (tid < 32) {
        float t = (tid < 8) ? sred[tid] : 0.f;
#pragma unroll
        for (int o = 4; o; o >>= 1) t += __shfl_xor_sync(0xffffffffu, t, o);
        if (tid == 0) sred[0] = t;
    }
    __syncthreads();
    r = sred[0];
    __syncthreads();
    return r;
}

__global__ __launch_bounds__(256)
void ln_kernel(const float* __restrict__ ln_w, const float* __restrict__ ln_b)
{
    __shared__ float sred[8];
    const int row = blockIdx.x;
    const int tid = threadIdx.x;
    const int b = row >> 11, n = row & 2047;

    const float4 v = ((const float4*)(g_attn + (size_t)row * Dd))[tid];
    float s = v.x + v.y + v.z + v.w;
    const float mu = block_reduce_256(s, sred, tid) * (1.f / 1024.f);

    const float dx = v.x - mu, dy = v.y - mu, dz = v.z - mu, dw = v.w - mu;
    float s2 = dx * dx + dy * dy + dz * dz + dw * dw;
    const float var = block_reduce_256(s2, sred, tid) * (1.f / 1024.f);
    const float rstd = rsqrtf(var + 1e-5f);

    const float4 w4 = ((const float4*)ln_w)[tid];
    const float4 b4 = ((const float4*)ln_b)[tid];
    const float4 u4 = ((const float4*)(g_qkvu + ((size_t)b * Nn + n) * 4096 + 3 * Dd))[tid];

    float4 o;
    o.x = roundtf((dx * rstd * w4.x + b4.x) * u4.x);
    o.y = roundtf((dy * rstd * w4.y + b4.y) * u4.y);
    o.z = roundtf((dz * rstd * w4.z + b4.z) * u4.z);
    o.w = roundtf((dw * rstd * w4.w + b4.w) * u4.w);
    ((float4*)(g_norm + (size_t)row * Dd))[tid] = o;
}

// ---------------------------------------------------------------------------
extern "C" void kernel_launch(void* const* d_in, const int* in_sizes, int n_in,
                              void* d_out, int out_size)
{
    const float* x     = (const float*)d_in[0];
    // d_in[1] = context (unused by reference)
    const float* Wqkvu = (const float*)d_in[2];
    const float* bqkvu = (const float*)d_in[3];
    const float* Wout  = (const float*)d_in[4];
    const float* bout  = (const float*)d_in[5];
    const float* theta = (const float*)d_in[6];
    const float* ln_w  = (const float*)d_in[7];
    const float* ln_b  = (const float*)d_in[8];
    float* out = (float*)d_out;

    float *qkvu_p, *norm_p, *xr_p, *wqr_p, *wor_p;
    cudaGetSymbolAddress((void**)&qkvu_p, g_qkvu);
    cudaGetSymbolAddress((void**)&norm_p, g_norm);
    cudaGetSymbolAddress((void**)&xr_p, g_xr);
    cudaGetSymbolAddress((void**)&wqr_p, g_wqr);
    cudaGetSymbolAddress((void**)&wor_p, g_wor);

    cudaFuncSetAttribute(qout_kernel, cudaFuncAttributeMaxDynamicSharedMemorySize,
                         (128 + 64) * QSTR * 4);
    cudaFuncSetAttribute(tgemm_nt, cudaFuncAttributeMaxDynamicSharedMemorySize,
                         TG_SMEM);

    // 0. trig table + pre-rounding
    trig_kernel<<<(Hh * Nn * DH) / 256, 256>>>(theta);
    round_kernel<<<(MROWS * Dd / 4 + 255) / 256, 256>>>((const float4*)x, (float4*)xr_p, MROWS * Dd / 4);
    round_kernel<<<(4 * Dd * Dd / 4 + 255) / 256, 256>>>((const float4*)Wqkvu, (float4*)wqr_p, 4 * Dd * Dd / 4);
    round_kernel<<<(Dd * Dd / 4 + 255) / 256, 256>>>((const float4*)Wout, (float4*)wor_p, Dd * Dd / 4);

    // 1. qkvu = x @ Wqkvu^T + bqkvu   [4096 x 4096]
    {
        dim3 grid(4096 / 128, MROWS / 128);
        tgemm_nt<<<grid, 256, TG_SMEM>>>(xr_p, wqr_p, bqkvu, qkvu_p, MROWS, 4096, 1024);
    }
    // 2-3. KV^T partials + deterministic reduce (rounded)
    {
        dim3 grid(32, 8);
        kv_kernel<<<grid, 256>>>();
        kv_reduce<<<1024, 256>>>();
    }
    // 4. attn = q' @ KV  (tensor cores)
    {
        dim3 grid(32, Nn / 128);
        qout_kernel<<<grid, 256, (128 + 64) * QSTR * 4>>>();
    }
    // 5. LayerNorm + *u (rounded output)
    ln_kernel<<<MROWS, 256>>>(ln_w, ln_b);

    // 6. out = norm @ Wout^T + bout   [4096 x 1024]
    {
        dim3 grid(1024 / 128, MROWS / 128);
        tgemm_nt<<<grid, 256, TG_SMEM>>>(norm_p, wor_p, bout, out, MROWS, 1024, 1024);
    }
}

// round 14
// speedup vs baseline: 3.7184x; 1.4431x over previous
#include <cuda_runtime.h>
#include <cuda_fp16.h>
#include <cstdint>
#include <math.h>

// ---------------------------------------------------------------------------
// NormLinearAttention  B=2 N=2048 D=1024 H=16 DH=64
// R11: fp16 m16n8k16 GEMMs with the PROVEN R4 3-stage cp.async ring
//      (R10's 2-buffer lookahead-2 overwrote the live buffer -> garbage).
// ---------------------------------------------------------------------------

#define Bb 2
#define Nn 2048
#define Dd 1024
#define Hh 16
#define DH 64
#define MROWS (Bb*Nn)        // 4096

__device__ float  g_qkvu[(size_t)MROWS * 4 * Dd];    // 64 MB
__device__ float  g_kvp[8 * 32 * 64 * 128];           // 8 MB partial KV^T
__device__ float  g_kvT[32 * 64 * 128];               // 1 MB reduced KV^T
__device__ float  g_attn[(size_t)MROWS * Dd];         // 16 MB
__device__ float2 g_trig[(size_t)Hh * Nn * DH];       // 16 MB
__device__ __half g_xh[(size_t)MROWS * Dd];           // 8 MB  x (fp16)
__device__ __half g_wqh[(size_t)4 * Dd * Dd];         // 8 MB  Wqkvu (fp16)
__device__ __half g_woh[(size_t)Dd * Dd];             // 2 MB  Wout (fp16)
__device__ __half g_normh[(size_t)MROWS * Dd];        // 8 MB  LN output (fp16)

// ---------------------------------------------------------------------------
// helpers
// ---------------------------------------------------------------------------
__device__ __forceinline__ uint32_t f2tf32(float x) {
    uint32_t r;
    asm("cvt.rna.tf32.f32 %0, %1;" : "=r"(r) : "f"(x));
    return r;
}
__device__ __forceinline__ float roundtf(float x) {
    return __uint_as_float(f2tf32(x));
}

__device__ __forceinline__ void mma_tf32(float* c, const uint32_t* a, const uint32_t* b) {
    asm volatile(
        "mma.sync.aligned.m16n8k8.row.col.f32.tf32.tf32.f32 "
        "{%0,%1,%2,%3}, {%4,%5,%6,%7}, {%8,%9}, {%0,%1,%2,%3};"
        : "+f"(c[0]), "+f"(c[1]), "+f"(c[2]), "+f"(c[3])
        : "r"(a[0]), "r"(a[1]), "r"(a[2]), "r"(a[3]), "r"(b[0]), "r"(b[1]));
}

__device__ __forceinline__ void mma_f16(float* c, const uint32_t* a, const uint32_t* b) {
    asm volatile(
        "mma.sync.aligned.m16n8k16.row.col.f32.f16.f16.f32 "
        "{%0,%1,%2,%3}, {%4,%5,%6,%7}, {%8,%9}, {%0,%1,%2,%3};"
        : "+f"(c[0]), "+f"(c[1]), "+f"(c[2]), "+f"(c[3])
        : "r"(a[0]), "r"(a[1]), "r"(a[2]), "r"(a[3]), "r"(b[0]), "r"(b[1]));
}

__device__ __forceinline__ void cpa16(uint32_t dst, const void* src) {
    asm volatile("cp.async.cg.shared.global [%0], [%1], 16;" :: "r"(dst), "l"(src));
}
__device__ __forceinline__ void cpa_commit() { asm volatile("cp.async.commit_group;"); }
__device__ __forceinline__ void cpa_wait1()  { asm volatile("cp.async.wait_group 1;"); }

// ---------------------------------------------------------------------------
// fp32 -> fp16 conversion (elementwise)
// ---------------------------------------------------------------------------
__global__ __launch_bounds__(256)
void tohalf_kernel(const float4* __restrict__ src, __half2* __restrict__ dst, int n4)
{
    const int i = blockIdx.x * 256 + threadIdx.x;
    if (i < n4) {
        const float4 v = src[i];
        dst[2 * i]     = __floats2half2_rn(v.x, v.y);
        dst[2 * i + 1] = __floats2half2_rn(v.z, v.w);
    }
}

// ---------------------------------------------------------------------------
// FP16 GEMM (NT): C[m,n] = sum_k A[m,k]*B[n,k] + bias[n]; fp32 accum.
// Block 128x128, BK=32 halves, 256 threads (8 warps, warp tile 64x32),
// 3-stage cp.async ring (R4-proven structure), smem stride 40 halves.
// ---------------------------------------------------------------------------
#define HBK 32
#define HSTR 40                        // halves per smem row (80 B)
#define H_MAT_HALF (128 * HSTR)        // 5120 halves per matrix per stage
#define H_STG_HALF (2 * H_MAT_HALF)    // 10240 halves per stage (A then B)
#define H_STG_B (H_STG_HALF * 2)       // 20480 bytes per stage
#define H_SMEM_TOTAL (3 * H_STG_B)     // 61440 bytes

__global__ __launch_bounds__(256, 2)
void hgemm_nt(const __half* __restrict__ A, const __half* __restrict__ B,
              const float* __restrict__ bias, float* __restrict__ C,
              int M, int N, int K)
{
    extern __shared__ __half hsm[];

    const int tid = threadIdx.x;
    const int bm = blockIdx.y * 128;
    const int bn = blockIdx.x * 128;
    const int wid = tid >> 5, lane = tid & 31;
    const int g = lane >> 2, tg = lane & 3;
    const int wm = (wid >> 2) * 64;      // 0 or 64
    const int wn = (wid & 3) * 32;       // 0,32,64,96

    float acc[4][4][4];
#pragma unroll
    for (int mi = 0; mi < 4; mi++)
#pragma unroll
        for (int ni = 0; ni < 4; ni++)
#pragma unroll
            for (int j = 0; j < 4; j++) acc[mi][ni][j] = 0.f;

    // loader: tile = 128 rows x 32 halves = 512 x 16B chunks; 2/thread/matrix
    const int lrow = tid >> 2;           // 0..63 (rows lrow, lrow+64)
    const int lc8 = (tid & 3) * 8;       // half col 0,8,16,24
    const __half* Ag = A + (size_t)(bm + lrow) * K + lc8;
    const __half* Bg = B + (size_t)(bn + lrow) * K + lc8;

    const uint32_t sbase = (uint32_t)__cvta_generic_to_shared(hsm);
    const uint32_t dA0 = (lrow * HSTR + lc8) * 2;
    const uint32_t dA1 = ((lrow + 64) * HSTR + lc8) * 2;
    const uint32_t dB = H_MAT_HALF * 2;

    const int nt = K / HBK;

    // prologue: prefetch kt=0,1 into stages 0,1
#pragma unroll
    for (int s = 0; s < 2; s++) {
        const int koff = s * HBK;
        const uint32_t so = sbase + s * H_STG_B;
        cpa16(so + dA0, Ag + koff);
        cpa16(so + dA1, Ag + (size_t)64 * K + koff);
        cpa16(so + dB + dA0, Bg + koff);
        cpa16(so + dB + dA1, Bg + (size_t)64 * K + koff);
        cpa_commit();
    }

    int st = 0;
    for (int kt = 0; kt < nt; kt++) {
        cpa_wait1();
        __syncthreads();

        if (kt + 2 < nt) {
            const int koff = (kt + 2) * HBK;
            int sn = st + 2; if (sn >= 3) sn -= 3;
            const uint32_t so = sbase + sn * H_STG_B;
            cpa16(so + dA0, Ag + koff);
            cpa16(so + dA1, Ag + (size_t)64 * K + koff);
            cpa16(so + dB + dA0, Bg + koff);
            cpa16(so + dB + dA1, Bg + (size_t)64 * K + koff);
            cpa_commit();
        }

        const __half* a_s = hsm + st * H_STG_HALF;
        const __half* b_s = a_s + H_MAT_HALF;

#pragma unroll
        for (int ks = 0; ks < 2; ks++) {
            const int k0 = ks * 16;
            uint32_t af[4][4], bf[4][2];
#pragma unroll
            for (int mi = 0; mi < 4; mi++) {
                const int r0 = wm + mi * 16 + g;
                af[mi][0] = *(const uint32_t*)&a_s[r0 * HSTR + k0 + 2 * tg];
                af[mi][1] = *(const uint32_t*)&a_s[(r0 + 8) * HSTR + k0 + 2 * tg];
                af[mi][2] = *(const uint32_t*)&a_s[r0 * HSTR + k0 + 8 + 2 * tg];
                af[mi][3] = *(const uint32_t*)&a_s[(r0 + 8) * HSTR + k0 + 8 + 2 * tg];
            }
#pragma unroll
            for (int ni = 0; ni < 4; ni++) {
                const int c0 = wn + ni * 8 + g;
                bf[ni][0] = *(const uint32_t*)&b_s[c0 * HSTR + k0 + 2 * tg];
                bf[ni][1] = *(const uint32_t*)&b_s[c0 * HSTR + k0 + 8 + 2 * tg];
            }
#pragma unroll
            for (int mi = 0; mi < 4; mi++)
#pragma unroll
                for (int ni = 0; ni < 4; ni++)
                    mma_f16(acc[mi][ni], af[mi], bf[ni]);
        }
        if (++st == 3) st = 0;
    }

#pragma unroll
    for (int mi = 0; mi < 4; mi++) {
        const int row = bm + wm + mi * 16 + g;
#pragma unroll
        for (int ni = 0; ni < 4; ni++) {
            const int col = bn + wn + ni * 8 + 2 * tg;
            const float bx = bias[col], by = bias[col + 1];
            float2 v0 = make_float2(acc[mi][ni][0] + bx, acc[mi][ni][1] + by);
            float2 v1 = make_float2(acc[mi][ni][2] + bx, acc[mi][ni][3] + by);
            *(float2*)&C[(size_t)row * N + col] = v0;
            *(float2*)&C[(size_t)(row + 8) * N + col] = v1;
        }
    }
}

__device__ __forceinline__ float silu_f(float x) {
    return x / (1.f + expf(-x));
}

// ---------------------------------------------------------------------------
// trig table
// ---------------------------------------------------------------------------
__global__ __launch_bounds__(256)
void trig_kernel(const float* __restrict__ theta)
{
    const int idx = blockIdx.x * 256 + threadIdx.x;
    const int d = idx & 63;
    const int n = (idx >> 6) & 2047;
    const int h = idx >> 17;
    float sn, cs;
    sincosf(theta[h * DH + d] * (float)n, &sn, &cs);
    g_trig[idx] = make_float2(cs, sn);
}

// ---------------------------------------------------------------------------
// partial KV
// ---------------------------------------------------------------------------
__global__ __launch_bounds__(256)
void kv_kernel()
{
    const int bh = blockIdx.x;
    const int b = bh >> 4, h = bh & 15;
    const int chunk = blockIdx.y;
    const int tid = threadIdx.x;

    __shared__ float skq[16][128];
    __shared__ float sv[16][64];

    const int ddg = (tid >> 4) * 8;
    const int eg = (tid & 15) * 4;
    const float* base = g_qkvu + (size_t)b * Nn * 4096;
    const float2* trig = g_trig + (size_t)h * Nn * DH;

    float acc[8][4];
#pragma unroll
    for (int i = 0; i < 8; i++)
#pragma unroll
        for (int j = 0; j < 4; j++) acc[i][j] = 0.f;

    for (int n0 = chunk * 256; n0 < chunk * 256 + 256; n0 += 16) {
        __syncthreads();
#pragma unroll
        for (int it = 0; it < 4; it++) {
            const int item = tid + it * 256;
            const int nn = item >> 6;
            const int d = item & 63;
            const int n = n0 + nn;
            const float kraw = base[(size_t)n * 4096 + Dd + h * DH + d];
            const float s = silu_f(kraw);
            const float2 t = trig[(size_t)n * DH + d];
            skq[nn][d] = s * t.x;
            skq[nn][DH + d] = s * t.y;
            sv[nn][d] = base[(size_t)n * 4096 + 2 * Dd + h * DH + d];
        }
        __syncthreads();
#pragma unroll
        for (int nn = 0; nn < 16; nn++) {
            float a[8], v[4];
            *(float4*)&a[0] = *(const float4*)&skq[nn][ddg];
            *(float4*)&a[4] = *(const float4*)&skq[nn][ddg + 4];
            *(float4*)&v[0] = *(const float4*)&sv[nn][eg];
#pragma unroll
            for (int i = 0; i < 8; i++)
#pragma unroll
                for (int j = 0; j < 4; j++)
                    acc[i][j] = fmaf(a[i], v[j], acc[i][j]);
        }
    }

    float* outp = g_kvp + (size_t)chunk * (32 * 8192) + (size_t)bh * 8192;
#pragma unroll
    for (int i = 0; i < 8; i++)
#pragma unroll
        for (int j = 0; j < 4; j++)
            outp[(eg + j) * 128 + ddg + i] = acc[i][j];
}

__global__ __launch_bounds__(256)
void kv_reduce()
{
    const int i = blockIdx.x * 256 + threadIdx.x;
    float s = 0.f;
#pragma unroll
    for (int c = 0; c < 8; c++)
        s += g_kvp[(size_t)c * (32 * 8192) + i];
    g_kvT[i] = roundtf(s);
}

// ---------------------------------------------------------------------------
// qout (tf32 mma.sync)
// ---------------------------------------------------------------------------
#define QSTR 132

__global__ __launch_bounds__(256)
void qout_kernel()
{
    extern __shared__ float qsm[];
    float* sQ = qsm;
    float* sKVt = qsm + 128 * QSTR;

    const int bh = blockIdx.x;
    const int b = bh >> 4, h = bh & 15;
    const int n0 = blockIdx.y * 128;
    const int tid = threadIdx.x;
    const int wid = tid >> 5, lane = tid & 31;
    const int g = lane >> 2, tg = lane & 3;

    {
        const float4* src = (const float4*)(g_kvT + (size_t)bh * 8192);
        for (int i = tid; i < 2048; i += 256) {
            const int e = i >> 5;
            const int dc = (i & 31) * 4;
            *(float4*)&sKVt[e * QSTR + dc] = src[i];
        }
    }

    {
        const int token = tid >> 1;
        const int d0 = (tid & 1) * 32;
        const int n = n0 + token;
        const float* qrow = g_qkvu + ((size_t)b * Nn + n) * 4096 + h * DH + d0;
        const float2* trow = g_trig + ((size_t)h * Nn + n) * DH + d0;
        float* dst = sQ + token * QSTR;
#pragma unroll
        for (int d = 0; d < 32; d++) {
            const float s = silu_f(qrow[d]);
            const float2 t = trow[d];
            dst[d0 + d] = roundtf(s * t.x);
            dst[DH + d0 + d] = roundtf(s * t.y);
        }
    }
    __syncthreads();

    const int wm = (wid >> 1) * 32;
    const int wn = (wid & 1) * 32;

    float acc[2][4][4];
#pragma unroll
    for (int mi = 0; mi < 2; mi++)
#pragma unroll
        for (int ni = 0; ni < 4; ni++)
#pragma unroll
            for (int j = 0; j < 4; j++) acc[mi][ni][j] = 0.f;

#pragma unroll
    for (int k0 = 0; k0 < 128; k0 += 8) {
        uint32_t af[2][4], bf[4][2];
#pragma unroll
        for (int mi = 0; mi < 2; mi++) {
            const int r0 = wm + mi * 16 + g;
            af[mi][0] = __float_as_uint(sQ[r0 * QSTR + k0 + tg]);
            af[mi][1] = __float_as_uint(sQ[(r0 + 8) * QSTR + k0 + tg]);
            af[mi][2] = __float_as_uint(sQ[r0 * QSTR + k0 + tg + 4]);
            af[mi][3] = __float_as_uint(sQ[(r0 + 8) * QSTR + k0 + tg + 4]);
        }
#pragma unroll
        for (int ni = 0; ni < 4; ni++) {
            const int c0 = wn + ni * 8 + g;
            bf[ni][0] = __float_as_uint(sKVt[c0 * QSTR + k0 + tg]);
            bf[ni][1] = __float_as_uint(sKVt[c0 * QSTR + k0 + tg + 4]);
        }
#pragma unroll
        for (int mi = 0; mi < 2; mi++)
#pragma unroll
            for (int ni = 0; ni < 4; ni++)
                mma_tf32(acc[mi][ni], af[mi], bf[ni]);
    }

#pragma unroll
    for (int mi = 0; mi < 2; mi++) {
        const int row = n0 + wm + mi * 16 + g;
        float* base0 = g_attn + ((size_t)b * Nn + row) * Dd + h * DH;
        float* base1 = g_attn + ((size_t)b * Nn + row + 8) * Dd + h * DH;
#pragma unroll
        for (int ni = 0; ni < 4; ni++) {
            const int col = wn + ni * 8 + 2 * tg;
            *(float2*)&base0[col] = make_float2(acc[mi][ni][0], acc[mi][ni][1]);
            *(float2*)&base1[col] = make_float2(acc[mi][ni][2], acc[mi][ni][3]);
        }
    }
}

// ---------------------------------------------------------------------------
// LayerNorm + *u ; emits fp16 for GEMM2
// ---------------------------------------------------------------------------
__device__ __forceinline__ float block_reduce_256(float v, float* sred, int tid)
{
#pragma unroll
    for (int o = 16; o; o >>= 1) v += __shfl_xor_sync(0xffffffffu, v, o);
    if ((tid & 31) == 0) sred[tid >> 5] = v;
    __syncthreads();
    float r;
    if (tid < 32) {
        float t = (tid < 8) ? sred[tid] : 0.f;
#pragma unroll
        for (int o = 4; o; o >>= 1) t += __shfl_xor_sync(0xffffffffu, t, o);
        if (tid == 0) sred[0] = t;
    }
    __syncthreads();
    r = sred[0];
    __syncthreads();
    return r;
}

__global__ __launch_bounds__(256)
void ln_kernel(const float* __restrict__ ln_w, const float* __restrict__ ln_b)
{
    __shared__ float sred[8];
    const int row = blockIdx.x;
    const int tid = threadIdx.x;
    const int b = row >> 11, n = row & 2047;

    const float4 v = ((const float4*)(g_attn + (size_t)row * Dd))[tid];
    float s = v.x + v.y + v.z + v.w;
    const float mu = block_reduce_256(s, sred, tid) * (1.f / 1024.f);

    const float dx = v.x - mu, dy = v.y - mu, dz = v.z - mu, dw = v.w - mu;
    float s2 = dx * dx + dy * dy + dz * dz + dw * dw;
    const float var = block_reduce_256(s2, sred, tid) * (1.f / 1024.f);
    const float rstd = rsqrtf(var + 1e-5f);

    const float4 w4 = ((const float4*)ln_w)[tid];
    const float4 b4 = ((const float4*)ln_b)[tid];
    const float4 u4 = ((const float4*)(g_qkvu + ((size_t)b * Nn + n) * 4096 + 3 * Dd))[tid];

    const float ox = (dx * rstd * w4.x + b4.x) * u4.x;
    const float oy = (dy * rstd * w4.y + b4.y) * u4.y;
    const float oz = (dz * rstd * w4.z + b4.z) * u4.z;
    const float ow = (dw * rstd * w4.w + b4.w) * u4.w;

    __half2* dsth = (__half2*)(g_normh + (size_t)row * Dd);
    dsth[2 * tid]     = __floats2half2_rn(ox, oy);
    dsth[2 * tid + 1] = __floats2half2_rn(oz, ow);
}

// ---------------------------------------------------------------------------
extern "C" void kernel_launch(void* const* d_in, const int* in_sizes, int n_in,
                              void* d_out, int out_size)
{
    const float* x     = (const float*)d_in[0];
    const float* Wqkvu = (const float*)d_in[2];
    const float* bqkvu = (const float*)d_in[3];
    const float* Wout  = (const float*)d_in[4];
    const float* bout  = (const float*)d_in[5];
    const float* theta = (const float*)d_in[6];
    const float* ln_w  = (const float*)d_in[7];
    const float* ln_b  = (const float*)d_in[8];
    float* out = (float*)d_out;

    float *qkvu_p;
    __half *xh_p, *wqh_p, *woh_p, *normh_p;
    cudaGetSymbolAddress((void**)&qkvu_p, g_qkvu);
    cudaGetSymbolAddress((void**)&xh_p, g_xh);
    cudaGetSymbolAddress((void**)&wqh_p, g_wqh);
    cudaGetSymbolAddress((void**)&woh_p, g_woh);
    cudaGetSymbolAddress((void**)&normh_p, g_normh);

    cudaFuncSetAttribute(qout_kernel, cudaFuncAttributeMaxDynamicSharedMemorySize,
                         (128 + 64) * QSTR * 4);
    cudaFuncSetAttribute(hgemm_nt, cudaFuncAttributeMaxDynamicSharedMemorySize,
                         H_SMEM_TOTAL);

    // 0. trig table + fp16 conversion of GEMM operands
    trig_kernel<<<(Hh * Nn * DH) / 256, 256>>>(theta);
    tohalf_kernel<<<(MROWS * Dd / 4 + 255) / 256, 256>>>((const float4*)x, (__half2*)xh_p, MROWS * Dd / 4);
    tohalf_kernel<<<(4 * Dd * Dd / 4 + 255) / 256, 256>>>((const float4*)Wqkvu, (__half2*)wqh_p, 4 * Dd * Dd / 4);
    tohalf_kernel<<<(Dd * Dd / 4 + 255) / 256, 256>>>((const float4*)Wout, (__half2*)woh_p, Dd * Dd / 4);

    // 1. qkvu = x @ Wqkvu^T + bqkvu   [4096 x 4096]  (fp16 mma, 3-stage)
    {
        dim3 grid(4096 / 128, MROWS / 128);
        hgemm_nt<<<grid, 256, H_SMEM_TOTAL>>>(xh_p, wqh_p, bqkvu, qkvu_p, MROWS, 4096, 1024);
    }
    // 2-3. KV^T partials + reduce
    {
        dim3 grid(32, 8);
        kv_kernel<<<grid, 256>>>();
        kv_reduce<<<1024, 256>>>();
    }
    // 4. attn = q' @ KV  (tf32 mma)
    {
        dim3 grid(32, Nn / 128);
        qout_kernel<<<grid, 256, (128 + 64) * QSTR * 4>>>();
    }
    // 5. LayerNorm + *u -> fp16
    ln_kernel<<<MROWS, 256>>>(ln_w, ln_b);

    // 6. out = norm @ Wout^T + bout   [4096 x 1024]  (fp16 mma, 3-stage)
    {
        dim3 grid(1024 / 128, MROWS / 128);
        hgemm_nt<<<grid, 256, H_SMEM_TOTAL>>>(normh_p, woh_p, bout, out, MROWS, 1024, 1024);
    }
}